// round 1
// baseline (speedup 1.0000x reference)
#include <cuda_runtime.h>
#include <math.h>
#include <stdint.h>

// Problem constants
#define BSZ 128
#define PIX 196
#define EDIM 512
#define HDIM 512
#define ADIM 512
#define EMBD 512
#define VOC 32000
#define TT 20
#define ZDIM 1536   // [xemb(512), ctx(512), hn(512)]
#define G4 2048     // 4*H

// ---------------- device scratch (no runtime allocation allowed) ----------------
__device__ float g_mean[BSZ * EDIM];
__device__ float g_h[BSZ * HDIM];
__device__ float g_c[BSZ * HDIM];
__device__ float g_q[BSZ * ADIM];
__device__ float g_ctx[BSZ * EDIM];
__device__ float g_z[BSZ * ZDIM];
__device__ float g_gates[BSZ * G4];
__device__ float g_ka[BSZ * PIX * ADIM];          // 51.4 MB
__device__ float g_Wcat[G4 * ZDIM];               // packed [W_lih | W_lhh]
__device__ float g_scratch[(size_t)BSZ * TT * VOC]; // 327 MB, (b,t,v) contiguous
__device__ unsigned long long g_amax[BSZ];

__device__ __forceinline__ float sigmf(float x) { return 1.0f / (1.0f + expf(-x)); }

__device__ __forceinline__ unsigned long long amax_key(float v, int n) {
    unsigned u = __float_as_uint(v);
    u = (u & 0x80000000u) ? ~u : (u | 0x80000000u);
    return ((unsigned long long)u << 32) | (unsigned long long)(0xFFFFFFFFu - (unsigned)n);
}

// ---------------- generic fp32 SGEMM: C[M,N] = A[M,K] * B[N,K]^T (+ epilogue) -----
// BM=BN=128, BK=8, 256 threads, 8x8 per thread. Requires M%128==0, N%128==0, K%8==0
// (true for every call site here).
// MODE 0: C = acc + bias[n]
// MODE 1: gate: g_z[m][512+n] = sigmoid(acc+bias[n]) * g_ctx[m*512+n]   (C unused)
// MODE 2: C = acc + bias[n] + bias2[n]
// MODE 3: logits: g_scratch[m][t][n] = acc + bias[n], fused argmax -> g_amax
// MODE 4: v = acc + bias[n]; C[m*N+n] = v; g_z[m][1024+n] = v  (init hn)
template <int MODE>
__global__ __launch_bounds__(256)
void sgemm_nt(const float* __restrict__ A, const float* __restrict__ B,
              const float* __restrict__ bias, const float* __restrict__ bias2,
              float* __restrict__ C, int M, int N, int K, int t) {
    __shared__ float As[8][128];
    __shared__ float Bs[8][128];
    const int bm = blockIdx.y * 128;
    const int bn = blockIdx.x * 128;
    const int tid = threadIdx.x;
    const int tx = tid & 15;       // 0..15 -> n
    const int ty = tid >> 4;       // 0..15 -> m
    const int lrow = tid >> 1;     // 0..127
    const int lcol = (tid & 1) << 2;

    const float* Ap = A + (size_t)(bm + lrow) * K + lcol;
    const float* Bp = B + (size_t)(bn + lrow) * K + lcol;

    float acc[8][8];
#pragma unroll
    for (int i = 0; i < 8; i++)
#pragma unroll
        for (int j = 0; j < 8; j++) acc[i][j] = 0.0f;

    for (int k0 = 0; k0 < K; k0 += 8) {
        float4 av = *reinterpret_cast<const float4*>(Ap + k0);
        float4 bv = *reinterpret_cast<const float4*>(Bp + k0);
        As[lcol + 0][lrow] = av.x; As[lcol + 1][lrow] = av.y;
        As[lcol + 2][lrow] = av.z; As[lcol + 3][lrow] = av.w;
        Bs[lcol + 0][lrow] = bv.x; Bs[lcol + 1][lrow] = bv.y;
        Bs[lcol + 2][lrow] = bv.z; Bs[lcol + 3][lrow] = bv.w;
        __syncthreads();
#pragma unroll
        for (int k = 0; k < 8; k++) {
            float4 a0 = *reinterpret_cast<const float4*>(&As[k][ty * 8]);
            float4 a1 = *reinterpret_cast<const float4*>(&As[k][ty * 8 + 4]);
            float4 b0 = *reinterpret_cast<const float4*>(&Bs[k][tx * 8]);
            float4 b1 = *reinterpret_cast<const float4*>(&Bs[k][tx * 8 + 4]);
            float am[8] = {a0.x, a0.y, a0.z, a0.w, a1.x, a1.y, a1.z, a1.w};
            float bb[8] = {b0.x, b0.y, b0.z, b0.w, b1.x, b1.y, b1.z, b1.w};
#pragma unroll
            for (int i = 0; i < 8; i++)
#pragma unroll
                for (int j = 0; j < 8; j++) acc[i][j] = fmaf(am[i], bb[j], acc[i][j]);
        }
        __syncthreads();
    }

    const int row0 = bm + ty * 8;
    const int col0 = bn + tx * 8;
#pragma unroll
    for (int i = 0; i < 8; i++) {
        const int m = row0 + i;
        if (MODE == 3) {
            float bestv = -3.4e38f;
            int bestn = 0;
            float* srow = g_scratch + (size_t)m * (TT * VOC) + (size_t)t * VOC;
#pragma unroll
            for (int j = 0; j < 8; j++) {
                const int n = col0 + j;
                float v = acc[i][j] + bias[n];
                srow[n] = v;
                if (v > bestv) { bestv = v; bestn = n; }
            }
            unsigned long long key = amax_key(bestv, bestn);
#pragma unroll
            for (int o = 1; o < 16; o <<= 1) {
                unsigned long long other = __shfl_xor_sync(0xffffffffu, key, o);
                if (other > key) key = other;
            }
            if (tx == 0) atomicMax(&g_amax[m], key);
        } else {
#pragma unroll
            for (int j = 0; j < 8; j++) {
                const int n = col0 + j;
                float v = acc[i][j] + bias[n];
                if (MODE == 0) {
                    C[(size_t)m * N + n] = v;
                } else if (MODE == 1) {
                    float s = sigmf(v);
                    g_z[m * ZDIM + 512 + n] = s * g_ctx[m * 512 + n];
                } else if (MODE == 2) {
                    C[(size_t)m * N + n] = v + bias2[n];
                } else if (MODE == 4) {
                    C[(size_t)m * N + n] = v;
                    g_z[m * ZDIM + 1024 + n] = v;
                }
            }
        }
    }
}

// ---------------- small kernels ----------------
__global__ void k_mean(const float* __restrict__ feat) {
    int b = blockIdx.x, e = threadIdx.x;  // 512 threads
    const float* f = feat + (size_t)b * PIX * EDIM + e;
    float s = 0.0f;
    for (int p = 0; p < PIX; p++) s += f[(size_t)p * EDIM];
    g_mean[b * EDIM + e] = s * (1.0f / (float)PIX);
}

__global__ void k_x0(const int* __restrict__ captions, const float* __restrict__ emb) {
    int b = blockIdx.x, e = threadIdx.x;
    int tok = captions[b * TT];
    g_z[b * ZDIM + e] = emb[(size_t)tok * EMBD + e];
}

__global__ void k_pack(const float* __restrict__ Wlih, const float* __restrict__ Wlhh) {
    int i = blockIdx.x * blockDim.x + threadIdx.x;
    if (i >= G4 * ZDIM) return;
    int j = i / ZDIM, k = i - j * ZDIM;
    g_Wcat[i] = (k < 1024) ? Wlih[(size_t)j * 1024 + k] : Wlhh[(size_t)j * 512 + (k - 1024)];
}

// per-batch attention: e -> softmax -> ctx (block = 1 batch row, 512 threads)
__global__ __launch_bounds__(512)
void k_att(const float* __restrict__ feat, const float* __restrict__ Watt,
           const float* __restrict__ batt) {
    __shared__ float q_s[ADIM];
    __shared__ float w_s[ADIM];
    __shared__ float e_s[PIX];
    __shared__ float red[16];
    const int b = blockIdx.x, tid = threadIdx.x;
    const int warp = tid >> 5, lane = tid & 31;

    q_s[tid] = g_q[b * ADIM + tid];
    w_s[tid] = Watt[tid];
    __syncthreads();

    for (int p = warp; p < PIX; p += 16) {
        const float* kap = g_ka + ((size_t)(b * PIX + p)) * ADIM;
        float s = 0.0f;
        for (int a = lane; a < ADIM; a += 32) {
            float v = kap[a] + q_s[a];
            s += fmaxf(v, 0.0f) * w_s[a];
        }
#pragma unroll
        for (int o = 16; o; o >>= 1) s += __shfl_xor_sync(0xffffffffu, s, o);
        if (lane == 0) e_s[p] = s + batt[0];
    }
    __syncthreads();

    // softmax over 196
    float m = (tid < PIX) ? e_s[tid] : -3.4e38f;
#pragma unroll
    for (int o = 16; o; o >>= 1) m = fmaxf(m, __shfl_xor_sync(0xffffffffu, m, o));
    if (lane == 0) red[warp] = m;
    __syncthreads();
    if (tid == 0) {
        float v = red[0];
        for (int i = 1; i < 16; i++) v = fmaxf(v, red[i]);
        red[0] = v;
    }
    __syncthreads();
    m = red[0];
    float ex = (tid < PIX) ? expf(e_s[tid] - m) : 0.0f;
    float ssum = ex;
#pragma unroll
    for (int o = 16; o; o >>= 1) ssum += __shfl_xor_sync(0xffffffffu, ssum, o);
    __syncthreads();  // all threads done reading red[0]
    if (lane == 0) red[warp] = ssum;
    __syncthreads();
    if (tid == 0) {
        float v = 0.0f;
        for (int i = 0; i < 16; i++) v += red[i];
        red[0] = 1.0f / v;
    }
    __syncthreads();
    if (tid < PIX) e_s[tid] = ex * red[0];
    __syncthreads();

    // ctx[b, e] = sum_p alpha[p] * feature[b, p, e]
    float acc = 0.0f;
    const float* fb = feat + (size_t)b * PIX * EDIM + tid;
    for (int p = 0; p < PIX; p++) acc = fmaf(e_s[p], fb[(size_t)p * EDIM], acc);
    g_ctx[b * EDIM + tid] = acc;
}

__global__ void k_cell() {
    int i = blockIdx.x * blockDim.x + threadIdx.x;  // 65536
    int b = i >> 9, h = i & 511;
    const float* g = g_gates + b * G4;
    float gi = g[h], gf = g[512 + h], gg = g[1024 + h], go = g[1536 + h];
    float c = sigmf(gf) * g_c[i] + sigmf(gi) * tanhf(gg);
    float hn = sigmf(go) * tanhf(c);
    g_c[i] = c;
    g_h[i] = hn;
    g_z[b * ZDIM + 1024 + h] = hn;
    if (h == 0) g_amax[b] = 0ull;  // reset before the logits GEMM of this step
}

__global__ void k_emb(const float* __restrict__ emb) {
    int b = blockIdx.x, e = threadIdx.x;
    unsigned long long key = g_amax[b];
    int idx = (int)(0xFFFFFFFFu - (unsigned)(key & 0xFFFFFFFFull));
    g_z[b * ZDIM + e] = emb[(size_t)idx * EMBD + e];
}

// final transpose: scratch (b,t,v) -> out (b,v,t), coalesced writes via smem
__global__ __launch_bounds__(256)
void k_tr(float* __restrict__ out) {
    __shared__ float sm[256 * 21];
    const int b = blockIdx.y;
    const int v0 = blockIdx.x * 256;
    const int tid = threadIdx.x;
    const float* src = g_scratch + (size_t)b * TT * VOC;
#pragma unroll
    for (int t = 0; t < TT; t++) sm[tid * 21 + t] = src[(size_t)t * VOC + v0 + tid];
    __syncthreads();
    float* ob = out + (size_t)b * VOC * TT + (size_t)v0 * TT;
    for (int e = tid; e < 256 * TT; e += 256) {
        int v = e / TT, t = e - v * TT;
        ob[e] = sm[v * 21 + t];
    }
}

// ---------------- host launch ----------------
static inline void* sym_addr(const void* symbol) {
    void* p = nullptr;
    cudaGetSymbolAddress(&p, symbol);
    return p;
}

extern "C" void kernel_launch(void* const* d_in, const int* in_sizes, int n_in,
                              void* d_out, int out_size) {
    const float* feat    = (const float*)d_in[0];
    const int*   caps    = (const int*)d_in[1];
    const float* W_ienc  = (const float*)d_in[2];
    const float* b_ienc  = (const float*)d_in[3];
    const float* W_oenc  = (const float*)d_in[4];
    const float* b_oenc  = (const float*)d_in[5];
    const float* W_att   = (const float*)d_in[6];
    const float* b_att   = (const float*)d_in[7];
    const float* W_inith = (const float*)d_in[8];
    const float* b_inith = (const float*)d_in[9];
    const float* W_initc = (const float*)d_in[10];
    const float* b_initc = (const float*)d_in[11];
    const float* W_gate  = (const float*)d_in[12];
    const float* b_gate  = (const float*)d_in[13];
    const float* embT    = (const float*)d_in[14];
    const float* W_lih   = (const float*)d_in[15];
    const float* W_lhh   = (const float*)d_in[16];
    const float* b_lih   = (const float*)d_in[17];
    const float* b_lhh   = (const float*)d_in[18];
    const float* W_out   = (const float*)d_in[19];
    const float* b_out   = (const float*)d_in[20];
    float* out = (float*)d_out;

    float* p_mean  = (float*)sym_addr(g_mean);
    float* p_h     = (float*)sym_addr(g_h);
    float* p_c     = (float*)sym_addr(g_c);
    float* p_q     = (float*)sym_addr(g_q);
    float* p_ctx   = (float*)sym_addr(g_ctx);
    float* p_z     = (float*)sym_addr(g_z);
    float* p_gates = (float*)sym_addr(g_gates);
    float* p_ka    = (float*)sym_addr(g_ka);
    float* p_Wcat  = (float*)sym_addr(g_Wcat);

    dim3 blk(256);

    // ---- setup (once per replay) ----
    k_mean<<<BSZ, 512>>>(feat);
    // hn0 = mean @ W_inith^T (also into g_z[:,1024:]); cn0 = mean @ W_initc^T
    sgemm_nt<4><<<dim3(HDIM / 128, 1), blk>>>(p_mean, W_inith, b_inith, nullptr, p_h,
                                              BSZ, HDIM, EDIM, 0);
    sgemm_nt<0><<<dim3(HDIM / 128, 1), blk>>>(p_mean, W_initc, b_initc, nullptr, p_c,
                                              BSZ, HDIM, EDIM, 0);
    // ka = feature @ W_ienc^T  (25088 x 512)
    sgemm_nt<0><<<dim3(ADIM / 128, (BSZ * PIX) / 128), blk>>>(feat, W_ienc, b_ienc, nullptr,
                                                              p_ka, BSZ * PIX, ADIM, EDIM, 0);
    k_x0<<<BSZ, 512>>>(caps, embT);
    k_pack<<<(G4 * ZDIM + 255) / 256, 256>>>(W_lih, W_lhh);

    // ---- T recurrent steps ----
    for (int t = 0; t < TT; t++) {
        // q = hn @ W_oenc^T + b_oenc
        sgemm_nt<0><<<dim3(ADIM / 128, 1), blk>>>(p_h, W_oenc, b_oenc, nullptr, p_q,
                                                  BSZ, ADIM, HDIM, 0);
        // attention -> g_ctx
        k_att<<<BSZ, 512>>>(feat, W_att, b_att);
        // gated ctx -> g_z[:,512:1024]
        sgemm_nt<1><<<dim3(EDIM / 128, 1), blk>>>(p_ctx, W_gate, b_gate, nullptr, nullptr,
                                                  BSZ, EDIM, EDIM, 0);
        // gates = z @ Wcat^T + b_lih + b_lhh
        sgemm_nt<2><<<dim3(G4 / 128, 1), blk>>>(p_z, p_Wcat, b_lih, b_lhh, p_gates,
                                                BSZ, G4, ZDIM, 0);
        // LSTM cell: update hn, cn (+ g_z hn slot, + amax reset)
        k_cell<<<(BSZ * HDIM) / 256, 256>>>();
        // logits = hn2 @ W_out^T + b_out -> scratch(b,t,v), fused argmax
        sgemm_nt<3><<<dim3(VOC / 128, 1), blk>>>(p_h, W_out, b_out, nullptr, nullptr,
                                                 BSZ, VOC, HDIM, t);
        // next-step embedding from argmax
        if (t < TT - 1) k_emb<<<BSZ, 512>>>(embT);
    }

    // ---- final transpose (b,t,v) -> (b,v,t) ----
    k_tr<<<dim3(VOC / 256, BSZ), 256>>>(out);
}

// round 2
// speedup vs baseline: 2.2152x; 2.2152x over previous
#include <cuda_runtime.h>
#include <math.h>
#include <stdint.h>

// Problem constants
#define BSZ 128
#define PIX 196
#define EDIM 512
#define HDIM 512
#define ADIM 512
#define EMBD 512
#define VOC 32000
#define TT 20
#define ZDIM 1536   // [xemb(512), ctx(512), hn(512)]
#define G4 2048     // 4*H

// ---------------- device scratch (no runtime allocation allowed) ----------------
__device__ float g_mean[BSZ * EDIM];
__device__ float g_h[BSZ * HDIM];
__device__ float g_c[BSZ * HDIM];
__device__ float g_q[BSZ * ADIM];
__device__ float g_ctx[BSZ * EDIM];
__device__ float g_z[BSZ * ZDIM];
__device__ float g_gates[BSZ * G4];
__device__ float g_ka[BSZ * PIX * ADIM];          // 51.4 MB
__device__ float g_Wcat[G4 * ZDIM];               // packed [W_lih | W_lhh]
__device__ float g_scratch[(size_t)BSZ * TT * VOC]; // 327 MB, (b,t,v) contiguous
__device__ unsigned long long g_amax[BSZ];

__device__ __forceinline__ float sigmf(float x) { return 1.0f / (1.0f + expf(-x)); }

__device__ __forceinline__ unsigned long long amax_key(float v, int n) {
    unsigned u = __float_as_uint(v);
    u = (u & 0x80000000u) ? ~u : (u | 0x80000000u);
    return ((unsigned long long)u << 32) | (unsigned long long)(0xFFFFFFFFu - (unsigned)n);
}

// ================= big-tile fp32 SGEMM: C[M,N] = A[M,K]*B[N,K]^T ================
// BM=BN=128, BK=8, 256 threads, 8x8/thread. Used only where it's throughput-bound
// with a full chip: ka (784 blocks) and logits (250 blocks, 2 CTA/SM -> 1 wave).
// MODE 0: C = acc + bias[n]
// MODE 3: logits: g_scratch[m][t][n] = acc + bias[n], fused argmax -> g_amax
template <int MODE>
__global__ __launch_bounds__(256)
void sgemm_nt(const float* __restrict__ A, const float* __restrict__ B,
              const float* __restrict__ bias, float* __restrict__ C,
              int M, int N, int K, int t) {
    __shared__ float As[8][128];
    __shared__ float Bs[8][128];
    const int bm = blockIdx.y * 128;
    const int bn = blockIdx.x * 128;
    const int tid = threadIdx.x;
    const int tx = tid & 15;       // 0..15 -> n
    const int ty = tid >> 4;       // 0..15 -> m
    const int lrow = tid >> 1;     // 0..127
    const int lcol = (tid & 1) << 2;

    const float* Ap = A + (size_t)(bm + lrow) * K + lcol;
    const float* Bp = B + (size_t)(bn + lrow) * K + lcol;

    float acc[8][8];
#pragma unroll
    for (int i = 0; i < 8; i++)
#pragma unroll
        for (int j = 0; j < 8; j++) acc[i][j] = 0.0f;

    for (int k0 = 0; k0 < K; k0 += 8) {
        float4 av = *reinterpret_cast<const float4*>(Ap + k0);
        float4 bv = *reinterpret_cast<const float4*>(Bp + k0);
        As[lcol + 0][lrow] = av.x; As[lcol + 1][lrow] = av.y;
        As[lcol + 2][lrow] = av.z; As[lcol + 3][lrow] = av.w;
        Bs[lcol + 0][lrow] = bv.x; Bs[lcol + 1][lrow] = bv.y;
        Bs[lcol + 2][lrow] = bv.z; Bs[lcol + 3][lrow] = bv.w;
        __syncthreads();
#pragma unroll
        for (int k = 0; k < 8; k++) {
            float4 a0 = *reinterpret_cast<const float4*>(&As[k][ty * 8]);
            float4 a1 = *reinterpret_cast<const float4*>(&As[k][ty * 8 + 4]);
            float4 b0 = *reinterpret_cast<const float4*>(&Bs[k][tx * 8]);
            float4 b1 = *reinterpret_cast<const float4*>(&Bs[k][tx * 8 + 4]);
            float am[8] = {a0.x, a0.y, a0.z, a0.w, a1.x, a1.y, a1.z, a1.w};
            float bb[8] = {b0.x, b0.y, b0.z, b0.w, b1.x, b1.y, b1.z, b1.w};
#pragma unroll
            for (int i = 0; i < 8; i++)
#pragma unroll
                for (int j = 0; j < 8; j++) acc[i][j] = fmaf(am[i], bb[j], acc[i][j]);
        }
        __syncthreads();
    }

    const int row0 = bm + ty * 8;
    const int col0 = bn + tx * 8;
#pragma unroll
    for (int i = 0; i < 8; i++) {
        const int m = row0 + i;
        if (MODE == 3) {
            float bestv = -3.4e38f;
            int bestn = 0;
            float* srow = g_scratch + (size_t)m * (TT * VOC) + (size_t)t * VOC;
#pragma unroll
            for (int j = 0; j < 8; j++) {
                const int n = col0 + j;
                float v = acc[i][j] + bias[n];
                srow[n] = v;
                if (v > bestv) { bestv = v; bestn = n; }
            }
            unsigned long long key = amax_key(bestv, bestn);
#pragma unroll
            for (int o = 1; o < 16; o <<= 1) {
                unsigned long long other = __shfl_xor_sync(0xffffffffu, key, o);
                if (other > key) key = other;
            }
            if (tx == 0) atomicMax(&g_amax[m], key);
        } else {
#pragma unroll
            for (int j = 0; j < 8; j++) {
                const int n = col0 + j;
                C[(size_t)m * N + n] = acc[i][j] + bias[n];
            }
        }
    }
}

// ================= small-M latency-optimized GEMM =================
// C[M,N] = A[M,K]*B[N,K]^T. BM=16, BN=64, BK=32, 128 threads, 2x4/thread.
// Grid (N/64, M/16) -> 64..512 blocks: fills the chip, per-block serial work
// is tiny (<= 1.6M MAC). Used for all the M=128 recurrent GEMMs.
// MODE 0: C = acc + bias[n]
// MODE 1: g_z[m][512+n] = sigmoid(acc+bias[n]) * g_ctx[m*512+n]
// MODE 2: C = acc + bias[n] + bias2[n]
// MODE 4: v = acc + bias[n]; C[m*N+n] = v; g_z[m][1024+n] = v   (init hn)
template <int MODE>
__global__ __launch_bounds__(128)
void gemm_small(const float* __restrict__ A, const float* __restrict__ B,
                const float* __restrict__ bias, const float* __restrict__ bias2,
                float* __restrict__ C, int M, int N, int K) {
    __shared__ float As[32][16];
    __shared__ float Bs[32][64];
    const int bn = blockIdx.x * 64;
    const int bm = blockIdx.y * 16;
    const int t = threadIdx.x;
    const int tx = t & 15;         // output col group (4 floats)
    const int ty = t >> 4;         // output row pair
    const int ar = t >> 3;         // A-load row (16 rows, 8 thr/row)
    const int ac = (t & 7) * 4;    // A-load col
    const int br = t >> 1;         // B-load row (64 rows, 2 thr/row)
    const int bc = (t & 1) * 16;   // B-load col (16 floats each)

    const float* Ap = A + (size_t)(bm + ar) * K + ac;
    const float* Bp = B + (size_t)(bn + br) * K + bc;

    float acc[2][4] = {};

    for (int k0 = 0; k0 < K; k0 += 32) {
        float4 av = *reinterpret_cast<const float4*>(Ap + k0);
        As[ac + 0][ar] = av.x; As[ac + 1][ar] = av.y;
        As[ac + 2][ar] = av.z; As[ac + 3][ar] = av.w;
        float4 b0 = *reinterpret_cast<const float4*>(Bp + k0);
        float4 b1 = *reinterpret_cast<const float4*>(Bp + k0 + 4);
        float4 b2 = *reinterpret_cast<const float4*>(Bp + k0 + 8);
        float4 b3 = *reinterpret_cast<const float4*>(Bp + k0 + 12);
        Bs[bc +  0][br] = b0.x; Bs[bc +  1][br] = b0.y;
        Bs[bc +  2][br] = b0.z; Bs[bc +  3][br] = b0.w;
        Bs[bc +  4][br] = b1.x; Bs[bc +  5][br] = b1.y;
        Bs[bc +  6][br] = b1.z; Bs[bc +  7][br] = b1.w;
        Bs[bc +  8][br] = b2.x; Bs[bc +  9][br] = b2.y;
        Bs[bc + 10][br] = b2.z; Bs[bc + 11][br] = b2.w;
        Bs[bc + 12][br] = b3.x; Bs[bc + 13][br] = b3.y;
        Bs[bc + 14][br] = b3.z; Bs[bc + 15][br] = b3.w;
        __syncthreads();
#pragma unroll
        for (int k = 0; k < 32; k++) {
            float a0 = As[k][2 * ty];
            float a1 = As[k][2 * ty + 1];
            float4 bv = *reinterpret_cast<const float4*>(&Bs[k][tx * 4]);
            acc[0][0] = fmaf(a0, bv.x, acc[0][0]);
            acc[0][1] = fmaf(a0, bv.y, acc[0][1]);
            acc[0][2] = fmaf(a0, bv.z, acc[0][2]);
            acc[0][3] = fmaf(a0, bv.w, acc[0][3]);
            acc[1][0] = fmaf(a1, bv.x, acc[1][0]);
            acc[1][1] = fmaf(a1, bv.y, acc[1][1]);
            acc[1][2] = fmaf(a1, bv.z, acc[1][2]);
            acc[1][3] = fmaf(a1, bv.w, acc[1][3]);
        }
        __syncthreads();
    }

    const int m0 = bm + 2 * ty;
    const int n0 = bn + 4 * tx;
#pragma unroll
    for (int r = 0; r < 2; r++) {
        const int m = m0 + r;
#pragma unroll
        for (int j = 0; j < 4; j++) {
            const int n = n0 + j;
            float v = acc[r][j] + bias[n];
            if (MODE == 0) {
                C[(size_t)m * N + n] = v;
            } else if (MODE == 1) {
                float s = sigmf(v);
                g_z[m * ZDIM + 512 + n] = s * g_ctx[m * 512 + n];
            } else if (MODE == 2) {
                C[(size_t)m * N + n] = v + bias2[n];
            } else if (MODE == 4) {
                C[(size_t)m * N + n] = v;
                g_z[m * ZDIM + 1024 + n] = v;
            }
        }
    }
}

// ---------------- small kernels ----------------
__global__ void k_mean(const float* __restrict__ feat) {
    int b = blockIdx.x, e = threadIdx.x;  // 512 threads
    const float* f = feat + (size_t)b * PIX * EDIM + e;
    float s = 0.0f;
    for (int p = 0; p < PIX; p++) s += f[(size_t)p * EDIM];
    g_mean[b * EDIM + e] = s * (1.0f / (float)PIX);
}

__global__ void k_x0(const int* __restrict__ captions, const float* __restrict__ emb) {
    int b = blockIdx.x, e = threadIdx.x;
    int tok = captions[b * TT];
    g_z[b * ZDIM + e] = emb[(size_t)tok * EMBD + e];
}

__global__ void k_pack(const float* __restrict__ Wlih, const float* __restrict__ Wlhh) {
    int i = blockIdx.x * blockDim.x + threadIdx.x;
    if (i >= G4 * ZDIM) return;
    int j = i / ZDIM, k = i - j * ZDIM;
    g_Wcat[i] = (k < 1024) ? Wlih[(size_t)j * 1024 + k] : Wlhh[(size_t)j * 512 + (k - 1024)];
}

// per-batch attention: e -> softmax -> ctx (block = 1 batch row, 512 threads)
__global__ __launch_bounds__(512)
void k_att(const float* __restrict__ feat, const float* __restrict__ Watt,
           const float* __restrict__ batt) {
    __shared__ float q_s[ADIM];
    __shared__ float w_s[ADIM];
    __shared__ float e_s[PIX];
    __shared__ float red[16];
    const int b = blockIdx.x, tid = threadIdx.x;
    const int warp = tid >> 5, lane = tid & 31;

    q_s[tid] = g_q[b * ADIM + tid];
    w_s[tid] = Watt[tid];
    __syncthreads();

    for (int p = warp; p < PIX; p += 16) {
        const float* kap = g_ka + ((size_t)(b * PIX + p)) * ADIM;
        float s = 0.0f;
        for (int a = lane; a < ADIM; a += 32) {
            float v = kap[a] + q_s[a];
            s += fmaxf(v, 0.0f) * w_s[a];
        }
#pragma unroll
        for (int o = 16; o; o >>= 1) s += __shfl_xor_sync(0xffffffffu, s, o);
        if (lane == 0) e_s[p] = s + batt[0];
    }
    __syncthreads();

    // softmax over 196
    float m = (tid < PIX) ? e_s[tid] : -3.4e38f;
#pragma unroll
    for (int o = 16; o; o >>= 1) m = fmaxf(m, __shfl_xor_sync(0xffffffffu, m, o));
    if (lane == 0) red[warp] = m;
    __syncthreads();
    if (tid == 0) {
        float v = red[0];
        for (int i = 1; i < 16; i++) v = fmaxf(v, red[i]);
        red[0] = v;
    }
    __syncthreads();
    m = red[0];
    float ex = (tid < PIX) ? expf(e_s[tid] - m) : 0.0f;
    float ssum = ex;
#pragma unroll
    for (int o = 16; o; o >>= 1) ssum += __shfl_xor_sync(0xffffffffu, ssum, o);
    __syncthreads();  // all threads done reading red[0]
    if (lane == 0) red[warp] = ssum;
    __syncthreads();
    if (tid == 0) {
        float v = 0.0f;
        for (int i = 0; i < 16; i++) v += red[i];
        red[0] = 1.0f / v;
    }
    __syncthreads();
    if (tid < PIX) e_s[tid] = ex * red[0];
    __syncthreads();

    // ctx[b, e] = sum_p alpha[p] * feature[b, p, e]
    float acc = 0.0f;
    const float* fb = feat + (size_t)b * PIX * EDIM + tid;
    for (int p = 0; p < PIX; p++) acc = fmaf(e_s[p], fb[(size_t)p * EDIM], acc);
    g_ctx[b * EDIM + tid] = acc;
}

__global__ void k_cell() {
    int i = blockIdx.x * blockDim.x + threadIdx.x;  // 65536
    int b = i >> 9, h = i & 511;
    const float* g = g_gates + b * G4;
    float gi = g[h], gf = g[512 + h], gg = g[1024 + h], go = g[1536 + h];
    float c = sigmf(gf) * g_c[i] + sigmf(gi) * tanhf(gg);
    float hn = sigmf(go) * tanhf(c);
    g_c[i] = c;
    g_h[i] = hn;
    g_z[b * ZDIM + 1024 + h] = hn;
    if (h == 0) g_amax[b] = 0ull;  // reset before the logits GEMM of this step
}

__global__ void k_emb(const float* __restrict__ emb) {
    int b = blockIdx.x, e = threadIdx.x;
    unsigned long long key = g_amax[b];
    int idx = (int)(0xFFFFFFFFu - (unsigned)(key & 0xFFFFFFFFull));
    g_z[b * ZDIM + e] = emb[(size_t)idx * EMBD + e];
}

// final transpose: scratch (b,t,v) -> out (b,v,t), coalesced writes via smem
__global__ __launch_bounds__(256)
void k_tr(float* __restrict__ out) {
    __shared__ float sm[256 * 21];
    const int b = blockIdx.y;
    const int v0 = blockIdx.x * 256;
    const int tid = threadIdx.x;
    const float* src = g_scratch + (size_t)b * TT * VOC;
#pragma unroll
    for (int t = 0; t < TT; t++) sm[tid * 21 + t] = src[(size_t)t * VOC + v0 + tid];
    __syncthreads();
    float* ob = out + (size_t)b * VOC * TT + (size_t)v0 * TT;
    for (int e = tid; e < 256 * TT; e += 256) {
        int v = e / TT, t = e - v * TT;
        ob[e] = sm[v * 21 + t];
    }
}

// ---------------- host launch ----------------
static inline void* sym_addr(const void* symbol) {
    void* p = nullptr;
    cudaGetSymbolAddress(&p, symbol);
    return p;
}

extern "C" void kernel_launch(void* const* d_in, const int* in_sizes, int n_in,
                              void* d_out, int out_size) {
    const float* feat    = (const float*)d_in[0];
    const int*   caps    = (const int*)d_in[1];
    const float* W_ienc  = (const float*)d_in[2];
    const float* b_ienc  = (const float*)d_in[3];
    const float* W_oenc  = (const float*)d_in[4];
    const float* b_oenc  = (const float*)d_in[5];
    const float* W_att   = (const float*)d_in[6];
    const float* b_att   = (const float*)d_in[7];
    const float* W_inith = (const float*)d_in[8];
    const float* b_inith = (const float*)d_in[9];
    const float* W_initc = (const float*)d_in[10];
    const float* b_initc = (const float*)d_in[11];
    const float* W_gate  = (const float*)d_in[12];
    const float* b_gate  = (const float*)d_in[13];
    const float* embT    = (const float*)d_in[14];
    const float* W_lih   = (const float*)d_in[15];
    const float* W_lhh   = (const float*)d_in[16];
    const float* b_lih   = (const float*)d_in[17];
    const float* b_lhh   = (const float*)d_in[18];
    const float* W_out   = (const float*)d_in[19];
    const float* b_out   = (const float*)d_in[20];
    float* out = (float*)d_out;

    float* p_mean  = (float*)sym_addr(g_mean);
    float* p_h     = (float*)sym_addr(g_h);
    float* p_c     = (float*)sym_addr(g_c);
    float* p_q     = (float*)sym_addr(g_q);
    float* p_ctx   = (float*)sym_addr(g_ctx);
    float* p_z     = (float*)sym_addr(g_z);
    float* p_gates = (float*)sym_addr(g_gates);
    float* p_ka    = (float*)sym_addr(g_ka);
    float* p_Wcat  = (float*)sym_addr(g_Wcat);

    // ---- setup (once per replay) ----
    k_mean<<<BSZ, 512>>>(feat);
    // hn0 = mean @ W_inith^T (also into g_z[:,1024:]); cn0 = mean @ W_initc^T
    gemm_small<4><<<dim3(HDIM / 64, BSZ / 16), 128>>>(p_mean, W_inith, b_inith, nullptr,
                                                      p_h, BSZ, HDIM, EDIM);
    gemm_small<0><<<dim3(HDIM / 64, BSZ / 16), 128>>>(p_mean, W_initc, b_initc, nullptr,
                                                      p_c, BSZ, HDIM, EDIM);
    // ka = feature @ W_ienc^T  (25088 x 512) — throughput-bound, big tiles
    sgemm_nt<0><<<dim3(ADIM / 128, (BSZ * PIX) / 128), 256>>>(feat, W_ienc, b_ienc,
                                                              p_ka, BSZ * PIX, ADIM, EDIM, 0);
    k_x0<<<BSZ, 512>>>(caps, embT);
    k_pack<<<(G4 * ZDIM + 255) / 256, 256>>>(W_lih, W_lhh);

    // ---- T recurrent steps ----
    for (int t = 0; t < TT; t++) {
        // q = hn @ W_oenc^T + b_oenc   (grid 64 blocks)
        gemm_small<0><<<dim3(ADIM / 64, BSZ / 16), 128>>>(p_h, W_oenc, b_oenc, nullptr,
                                                          p_q, BSZ, ADIM, HDIM);
        // attention -> g_ctx
        k_att<<<BSZ, 512>>>(feat, W_att, b_att);
        // gated ctx -> g_z[:,512:1024]   (grid 64 blocks)
        gemm_small<1><<<dim3(EDIM / 64, BSZ / 16), 128>>>(p_ctx, W_gate, b_gate, nullptr,
                                                          nullptr, BSZ, EDIM, EDIM);
        // gates = z @ Wcat^T + b_lih + b_lhh   (grid 256 blocks)
        gemm_small<2><<<dim3(G4 / 64, BSZ / 16), 128>>>(p_z, p_Wcat, b_lih, b_lhh,
                                                        p_gates, BSZ, G4, ZDIM);
        // LSTM cell: update hn, cn (+ g_z hn slot, + amax reset)
        k_cell<<<(BSZ * HDIM) / 256, 256>>>();
        // logits = hn2 @ W_out^T + b_out -> scratch(b,t,v), fused argmax
        sgemm_nt<3><<<dim3(VOC / 128, 1), 256>>>(p_h, W_out, b_out, nullptr,
                                                 BSZ, VOC, HDIM, t);
        // next-step embedding from argmax
        if (t < TT - 1) k_emb<<<BSZ, 512>>>(embT);
    }

    // ---- final transpose (b,t,v) -> (b,v,t) ----
    k_tr<<<dim3(VOC / 256, BSZ), 256>>>(out);
}

// round 4
// speedup vs baseline: 2.5960x; 1.1719x over previous
#include <cuda_runtime.h>
#include <math.h>
#include <stdint.h>

// Problem constants
#define BSZ 128
#define PIX 196
#define EDIM 512
#define HDIM 512
#define ADIM 512
#define EMBD 512
#define VOC 32000
#define TT 20
#define ZDIM 1536   // [xemb(512), ctx(512), hn(512)]
#define G4 2048     // 4*H

// Split-GEMM geometry: K' = 3*512 = 1536, 192 k-steps of 8
#define KP 1536
#define NKS 192
#define NTILES (VOC / 8)        // 4000 n-tiles of 8

// ---------------- device scratch (no runtime allocation allowed) ----------------
__device__ float g_mean[BSZ * EDIM];
__device__ float g_h[BSZ * HDIM];
__device__ float g_c[BSZ * HDIM];
__device__ float g_q[BSZ * ADIM];
__device__ float g_ctx[BSZ * EDIM];
__device__ float g_z[BSZ * ZDIM];
__device__ float g_gates[BSZ * G4];
__device__ float g_ka[BSZ * PIX * ADIM];            // 51.4 MB
__device__ float g_Wcat[G4 * ZDIM];                 // packed [W_lih | W_lhh]
__device__ float g_scratch[(size_t)BSZ * TT * VOC]; // 327 MB, (b,t,v)
__device__ unsigned long long g_amax[BSZ];
// mma-fragment-ordered operands for the tf32-split logits GEMM
__device__ float  g_Afrag[8 * NKS * 32 * 4];        // 786 KB  [mt][ks][lane][4]
__device__ float2 g_Bfrag[(size_t)NTILES * NKS * 32]; // 196.6 MB [nt][ks][lane]{b0,b1}

__device__ __forceinline__ float sigmf(float x) { return 1.0f / (1.0f + expf(-x)); }

__device__ __forceinline__ float tf32r(float x) {
    uint32_t u;
    asm("cvt.rna.tf32.f32 %0, %1;" : "=r"(u) : "f"(x));
    return __uint_as_float(u);
}

__device__ __forceinline__ unsigned long long amax_key(float v, int n) {
    unsigned u = __float_as_uint(v);
    u = (u & 0x80000000u) ? ~u : (u | 0x80000000u);
    return ((unsigned long long)u << 32) | (unsigned long long)(0xFFFFFFFFu - (unsigned)n);
}

// A-fragment slot for logical A'[m][kp] (m16n8k8.row.col tf32 layout)
__device__ __forceinline__ void write_afrag(int m, int kp, float v) {
    const int mt = m >> 4, r = m & 15, g = r & 7, regM = r >> 3;
    const int ks = kp >> 3, t4 = kp & 3, regK = (kp >> 2) & 1;
    g_Afrag[(((mt * NKS + ks) * 32) + 4 * g + t4) * 4 + regK * 2 + regM] = v;
}

// ---------------- cp.async helpers (sm_80 base features) ----------------
__device__ __forceinline__ uint32_t smem_u32(const void* p) {
    uint32_t a;
    asm("{ .reg .u64 t; cvta.to.shared.u64 t, %1; cvt.u32.u64 %0, t; }" : "=r"(a) : "l"(p));
    return a;
}
__device__ __forceinline__ void cp16(uint32_t s, const void* g) {
    asm volatile("cp.async.cg.shared.global [%0], [%1], 16;" :: "r"(s), "l"(g));
}
__device__ __forceinline__ void cp8(uint32_t s, const void* g) {
    asm volatile("cp.async.ca.shared.global [%0], [%1], 8;" :: "r"(s), "l"(g));
}
__device__ __forceinline__ void cp_commit() {
    asm volatile("cp.async.commit_group;" ::: "memory");
}
template <int N>
__device__ __forceinline__ void cp_wait() {
    asm volatile("cp.async.wait_group %0;" :: "n"(N) : "memory");
}

__device__ __forceinline__ void mma_tf32(float& c0, float& c1, float& c2, float& c3,
                                         uint32_t a0, uint32_t a1, uint32_t a2, uint32_t a3,
                                         uint32_t b0, uint32_t b1) {
    asm volatile(
        "mma.sync.aligned.m16n8k8.row.col.f32.tf32.tf32.f32 "
        "{%0,%1,%2,%3}, {%4,%5,%6,%7}, {%8,%9}, {%0,%1,%2,%3};"
        : "+f"(c0), "+f"(c1), "+f"(c2), "+f"(c3)
        : "r"(a0), "r"(a1), "r"(a2), "r"(a3), "r"(b0), "r"(b1));
}

// ================= tensor-core (mma.sync tf32) logits GEMM =================
// C[128 batch, 128 voc] = A'[128,1536] * B'[128,1536]^T + bias, fused argmax.
// Operands pre-fragmented; smem stages are raw linear fragment blobs.
// Stage = 4 ksteps: A 16KB + B 16KB. 2 stages (64KB). Epilogue reuses smem (66KB).
#define L_STAGE_B 32768
#define L_NCHUNK 48          // 192 / 4
#define L_SMEM 69632         // 68 KB (>= 128*132*4 = 67584 epilogue)

__global__ void __launch_bounds__(256, 2)
logits_mma(const float* __restrict__ bias, int t) {
    extern __shared__ char sm[];
    const uint32_t sb32 = smem_u32(sm);
    const int tid = threadIdx.x;
    const int wid = tid >> 5, lane = tid & 31;
    const int warpM = wid >> 2, warpN = wid & 3;   // 2 x 4 warp grid
    const int nb0 = blockIdx.x * 16;               // first n-tile of this CTA
    const int n0 = blockIdx.x * 128;

    float c[4][4][4];
#pragma unroll
    for (int mi = 0; mi < 4; mi++)
#pragma unroll
        for (int ni = 0; ni < 4; ni++)
#pragma unroll
            for (int r = 0; r < 4; r++) c[mi][ni][r] = 0.0f;

    // ---- stage loader: chunk cc covers ksteps [cc*4, cc*4+4) ----
    auto load_stage = [&](int cc) {
        const int ks0 = cc * 4;
        const uint32_t base = sb32 + (cc & 1) * L_STAGE_B;
#pragma unroll
        for (int i = 0; i < 4; i++) {              // A: 1024 x 16B
            const int idx = tid + i * 256;
            const int mt = idx >> 7, rem = idx & 127;
            const int ksl = rem >> 5, ln = rem & 31;
            cp16(base + idx * 16,
                 g_Afrag + ((mt * NKS + ks0 + ksl) * 32 + ln) * 4);
        }
#pragma unroll
        for (int i = 0; i < 8; i++) {              // B: 2048 x 8B
            const int idx = tid + i * 256;
            const int ntl = idx >> 7;
            const int ksl = (idx >> 5) & 3, ln = idx & 31;
            cp8(base + 16384 + idx * 8,
                g_Bfrag + ((size_t)(nb0 + ntl) * NKS + ks0 + ksl) * 32 + ln);
        }
        cp_commit();
    };

    load_stage(0);
    for (int cc = 0; cc < L_NCHUNK; cc++) {
        if (cc + 1 < L_NCHUNK) { load_stage(cc + 1); cp_wait<1>(); }
        else                   { cp_wait<0>(); }
        __syncthreads();
        const char* buf = sm + (cc & 1) * L_STAGE_B;
#pragma unroll
        for (int ksl = 0; ksl < 4; ksl++) {
            uint4 af[4];
            uint2 bf[4];
#pragma unroll
            for (int mi = 0; mi < 4; mi++) {
                const int mt = warpM * 4 + mi;
                af[mi] = *(const uint4*)(buf + ((mt * 4 + ksl) * 32 + lane) * 16);
            }
#pragma unroll
            for (int ni = 0; ni < 4; ni++) {
                const int nt = warpN * 4 + ni;
                bf[ni] = *(const uint2*)(buf + 16384 + ((nt * 4 + ksl) * 32 + lane) * 8);
            }
#pragma unroll
            for (int mi = 0; mi < 4; mi++)
#pragma unroll
                for (int ni = 0; ni < 4; ni++)
                    mma_tf32(c[mi][ni][0], c[mi][ni][1], c[mi][ni][2], c[mi][ni][3],
                             af[mi].x, af[mi].y, af[mi].z, af[mi].w,
                             bf[ni].x, bf[ni].y);
        }
        __syncthreads();
    }

    // ---- epilogue: stage C in smem, argmax, coalesced scratch store ----
    float* st = (float*)sm;                         // 128 x 132
    const int g = lane >> 2, t4 = lane & 3;
#pragma unroll
    for (int mi = 0; mi < 4; mi++) {
        const int m = warpM * 64 + mi * 16 + g;
#pragma unroll
        for (int ni = 0; ni < 4; ni++) {
            const int col = warpN * 32 + ni * 8 + 2 * t4;
            st[m * 132 + col]           = c[mi][ni][0];
            st[m * 132 + col + 1]       = c[mi][ni][1];
            st[(m + 8) * 132 + col]     = c[mi][ni][2];
            st[(m + 8) * 132 + col + 1] = c[mi][ni][3];
        }
    }
    __syncthreads();

    {   // per-row argmax: 2 threads per row, 64 cols each
        const int row = tid & 127;
        const int c0 = (tid >> 7) * 64;
        float bestv = -3.4e38f;
        int bestn = 0;
#pragma unroll 8
        for (int cc2 = 0; cc2 < 64; cc2++) {
            const int col = c0 + cc2;
            float v = st[row * 132 + col] + __ldg(&bias[n0 + col]);
            if (v > bestv) { bestv = v; bestn = n0 + col; }
        }
        atomicMax(&g_amax[row], amax_key(bestv, bestn));
    }
    for (int idx = tid; idx < 128 * 128; idx += 256) {
        const int m2 = idx >> 7, cc2 = idx & 127;
        g_scratch[((size_t)m2 * TT + t) * VOC + n0 + cc2] =
            st[m2 * 132 + cc2] + __ldg(&bias[n0 + cc2]);
    }
}

// build B' fragments from W_out (once per launch)
// thread i -> (nt, ks, lane); b0 = W'[8nt+g][8ks+t4], b1 = W'[..][+4]
__device__ __forceinline__ float wval(const float* __restrict__ W, int n, int kp) {
    if (kp < 512) return tf32r(W[(size_t)n * 512 + kp]);
    if (kp < 1024) {
        float x = W[(size_t)n * 512 + kp - 512];
        return tf32r(x - tf32r(x));
    }
    return tf32r(W[(size_t)n * 512 + kp - 1024]);
}
__global__ void k_bfrag(const float* __restrict__ W) {
    size_t i = (size_t)blockIdx.x * 256 + threadIdx.x;
    if (i >= (size_t)NTILES * NKS * 32) return;
    const int lane = (int)(i & 31);
    const size_t r = i >> 5;
    const int ks = (int)(r % NKS);
    const int nt = (int)(r / NKS);
    const int g = lane >> 2, t4 = lane & 3;
    const int n = nt * 8 + g;
    const int k1 = ks * 8 + t4;
    g_Bfrag[i] = make_float2(wval(W, n, k1), wval(W, n, k1 + 4));
}

// ================= big-tile fp32 SGEMM (ka only) ================
__global__ __launch_bounds__(256)
void sgemm_nt(const float* __restrict__ A, const float* __restrict__ B,
              const float* __restrict__ bias, float* __restrict__ C,
              int M, int N, int K) {
    __shared__ float As[8][128];
    __shared__ float Bs[8][128];
    const int bm = blockIdx.y * 128;
    const int bn = blockIdx.x * 128;
    const int tid = threadIdx.x;
    const int tx = tid & 15;
    const int ty = tid >> 4;
    const int lrow = tid >> 1;
    const int lcol = (tid & 1) << 2;

    const float* Ap = A + (size_t)(bm + lrow) * K + lcol;
    const float* Bp = B + (size_t)(bn + lrow) * K + lcol;

    float acc[8][8];
#pragma unroll
    for (int i = 0; i < 8; i++)
#pragma unroll
        for (int j = 0; j < 8; j++) acc[i][j] = 0.0f;

    for (int k0 = 0; k0 < K; k0 += 8) {
        float4 av = *reinterpret_cast<const float4*>(Ap + k0);
        float4 bv = *reinterpret_cast<const float4*>(Bp + k0);
        As[lcol + 0][lrow] = av.x; As[lcol + 1][lrow] = av.y;
        As[lcol + 2][lrow] = av.z; As[lcol + 3][lrow] = av.w;
        Bs[lcol + 0][lrow] = bv.x; Bs[lcol + 1][lrow] = bv.y;
        Bs[lcol + 2][lrow] = bv.z; Bs[lcol + 3][lrow] = bv.w;
        __syncthreads();
#pragma unroll
        for (int k = 0; k < 8; k++) {
            float4 a0 = *reinterpret_cast<const float4*>(&As[k][ty * 8]);
            float4 a1 = *reinterpret_cast<const float4*>(&As[k][ty * 8 + 4]);
            float4 b0 = *reinterpret_cast<const float4*>(&Bs[k][tx * 8]);
            float4 b1 = *reinterpret_cast<const float4*>(&Bs[k][tx * 8 + 4]);
            float am[8] = {a0.x, a0.y, a0.z, a0.w, a1.x, a1.y, a1.z, a1.w};
            float bb[8] = {b0.x, b0.y, b0.z, b0.w, b1.x, b1.y, b1.z, b1.w};
#pragma unroll
            for (int i = 0; i < 8; i++)
#pragma unroll
                for (int j = 0; j < 8; j++) acc[i][j] = fmaf(am[i], bb[j], acc[i][j]);
        }
        __syncthreads();
    }

    const int row0 = bm + ty * 8;
    const int col0 = bn + tx * 8;
#pragma unroll
    for (int i = 0; i < 8; i++) {
        const int mm = row0 + i;
#pragma unroll
        for (int j = 0; j < 8; j++) {
            const int n = col0 + j;
            C[(size_t)mm * N + n] = acc[i][j] + bias[n];
        }
    }
}

// ================= small-M latency-optimized GEMM =================
// MODE 0: C = acc + bias
// MODE 1: g_z[m][512+n] = sigmoid(acc+bias) * g_ctx
// MODE 2: C = acc + bias + bias2
// MODE 4: init hn: C + g_z hn slot + A-fragment writes
template <int MODE>
__global__ __launch_bounds__(128)
void gemm_small(const float* __restrict__ A, const float* __restrict__ B,
                const float* __restrict__ bias, const float* __restrict__ bias2,
                float* __restrict__ C, int M, int N, int K) {
    __shared__ float As[32][16];
    __shared__ float Bs[32][64];
    const int bn = blockIdx.x * 64;
    const int bm = blockIdx.y * 16;
    const int t = threadIdx.x;
    const int tx = t & 15;
    const int ty = t >> 4;
    const int ar = t >> 3;
    const int ac = (t & 7) * 4;
    const int br = t >> 1;
    const int bc = (t & 1) * 16;

    const float* Ap = A + (size_t)(bm + ar) * K + ac;
    const float* Bp = B + (size_t)(bn + br) * K + bc;

    float acc[2][4] = {};

    for (int k0 = 0; k0 < K; k0 += 32) {
        float4 av = *reinterpret_cast<const float4*>(Ap + k0);
        As[ac + 0][ar] = av.x; As[ac + 1][ar] = av.y;
        As[ac + 2][ar] = av.z; As[ac + 3][ar] = av.w;
        float4 b0 = *reinterpret_cast<const float4*>(Bp + k0);
        float4 b1 = *reinterpret_cast<const float4*>(Bp + k0 + 4);
        float4 b2 = *reinterpret_cast<const float4*>(Bp + k0 + 8);
        float4 b3 = *reinterpret_cast<const float4*>(Bp + k0 + 12);
        Bs[bc +  0][br] = b0.x; Bs[bc +  1][br] = b0.y;
        Bs[bc +  2][br] = b0.z; Bs[bc +  3][br] = b0.w;
        Bs[bc +  4][br] = b1.x; Bs[bc +  5][br] = b1.y;
        Bs[bc +  6][br] = b1.z; Bs[bc +  7][br] = b1.w;
        Bs[bc +  8][br] = b2.x; Bs[bc +  9][br] = b2.y;
        Bs[bc + 10][br] = b2.z; Bs[bc + 11][br] = b2.w;
        Bs[bc + 12][br] = b3.x; Bs[bc + 13][br] = b3.y;
        Bs[bc + 14][br] = b3.z; Bs[bc + 15][br] = b3.w;
        __syncthreads();
#pragma unroll
        for (int k = 0; k < 32; k++) {
            float a0 = As[k][2 * ty];
            float a1 = As[k][2 * ty + 1];
            float4 bv = *reinterpret_cast<const float4*>(&Bs[k][tx * 4]);
            acc[0][0] = fmaf(a0, bv.x, acc[0][0]);
            acc[0][1] = fmaf(a0, bv.y, acc[0][1]);
            acc[0][2] = fmaf(a0, bv.z, acc[0][2]);
            acc[0][3] = fmaf(a0, bv.w, acc[0][3]);
            acc[1][0] = fmaf(a1, bv.x, acc[1][0]);
            acc[1][1] = fmaf(a1, bv.y, acc[1][1]);
            acc[1][2] = fmaf(a1, bv.z, acc[1][2]);
            acc[1][3] = fmaf(a1, bv.w, acc[1][3]);
        }
        __syncthreads();
    }

    const int m0 = bm + 2 * ty;
    const int n0 = bn + 4 * tx;
#pragma unroll
    for (int r = 0; r < 2; r++) {
        const int m = m0 + r;
#pragma unroll
        for (int j = 0; j < 4; j++) {
            const int n = n0 + j;
            float v = acc[r][j] + bias[n];
            if (MODE == 0) {
                C[(size_t)m * N + n] = v;
            } else if (MODE == 1) {
                float s = sigmf(v);
                g_z[m * ZDIM + 512 + n] = s * g_ctx[m * 512 + n];
            } else if (MODE == 2) {
                C[(size_t)m * N + n] = v + bias2[n];
            } else if (MODE == 4) {
                C[(size_t)m * N + n] = v;
                g_z[m * ZDIM + 1024 + n] = v;
                float hi = tf32r(v);
                float lo = tf32r(v - hi);
                write_afrag(m, n, hi);
                write_afrag(m, n + 512, hi);
                write_afrag(m, n + 1024, lo);
            }
        }
    }
}

// ---------------- small kernels ----------------
__global__ void k_mean(const float* __restrict__ feat) {
    int b = blockIdx.x, e = threadIdx.x;
    const float* f = feat + (size_t)b * PIX * EDIM + e;
    float s = 0.0f;
    for (int p = 0; p < PIX; p++) s += f[(size_t)p * EDIM];
    g_mean[b * EDIM + e] = s * (1.0f / (float)PIX);
}

__global__ void k_x0(const int* __restrict__ captions, const float* __restrict__ emb) {
    int b = blockIdx.x, e = threadIdx.x;
    int tok = captions[b * TT];
    g_z[b * ZDIM + e] = emb[(size_t)tok * EMBD + e];
    if (e == 0) g_amax[b] = 0ull;  // reset for the t=0 logits pass
}

__global__ void k_pack(const float* __restrict__ Wlih, const float* __restrict__ Wlhh) {
    int i = blockIdx.x * blockDim.x + threadIdx.x;
    if (i >= G4 * ZDIM) return;
    int j = i / ZDIM, k = i - j * ZDIM;
    g_Wcat[i] = (k < 1024) ? Wlih[(size_t)j * 1024 + k] : Wlhh[(size_t)j * 512 + (k - 1024)];
}

// per-batch attention
__global__ __launch_bounds__(512)
void k_att(const float* __restrict__ feat, const float* __restrict__ Watt,
           const float* __restrict__ batt) {
    __shared__ float q_s[ADIM];
    __shared__ float w_s[ADIM];
    __shared__ float e_s[PIX];
    __shared__ float red[16];
    const int b = blockIdx.x, tid = threadIdx.x;
    const int warp = tid >> 5, lane = tid & 31;

    q_s[tid] = g_q[b * ADIM + tid];
    w_s[tid] = Watt[tid];
    __syncthreads();

    for (int p = warp; p < PIX; p += 16) {
        const float* kap = g_ka + ((size_t)(b * PIX + p)) * ADIM;
        float s = 0.0f;
        for (int a = lane; a < ADIM; a += 32) {
            float v = kap[a] + q_s[a];
            s += fmaxf(v, 0.0f) * w_s[a];
        }
#pragma unroll
        for (int o = 16; o; o >>= 1) s += __shfl_xor_sync(0xffffffffu, s, o);
        if (lane == 0) e_s[p] = s + batt[0];
    }
    __syncthreads();

    float m = (tid < PIX) ? e_s[tid] : -3.4e38f;
#pragma unroll
    for (int o = 16; o; o >>= 1) m = fmaxf(m, __shfl_xor_sync(0xffffffffu, m, o));
    if (lane == 0) red[warp] = m;
    __syncthreads();
    if (tid == 0) {
        float v = red[0];
        for (int i = 1; i < 16; i++) v = fmaxf(v, red[i]);
        red[0] = v;
    }
    __syncthreads();
    m = red[0];
    float ex = (tid < PIX) ? expf(e_s[tid] - m) : 0.0f;
    float ssum = ex;
#pragma unroll
    for (int o = 16; o; o >>= 1) ssum += __shfl_xor_sync(0xffffffffu, ssum, o);
    __syncthreads();
    if (lane == 0) red[warp] = ssum;
    __syncthreads();
    if (tid == 0) {
        float v = 0.0f;
        for (int i = 0; i < 16; i++) v += red[i];
        red[0] = 1.0f / v;
    }
    __syncthreads();
    if (tid < PIX) e_s[tid] = ex * red[0];
    __syncthreads();

    float acc = 0.0f;
    const float* fb = feat + (size_t)b * PIX * EDIM + tid;
    for (int p = 0; p < PIX; p++) acc = fmaf(e_s[p], fb[(size_t)p * EDIM], acc);
    g_ctx[b * EDIM + tid] = acc;
}

__global__ void k_cell() {
    int i = blockIdx.x * blockDim.x + threadIdx.x;
    int b = i >> 9, h = i & 511;
    const float* g = g_gates + b * G4;
    float gi = g[h], gf = g[512 + h], gg = g[1024 + h], go = g[1536 + h];
    float c = sigmf(gf) * g_c[i] + sigmf(gi) * tanhf(gg);
    float hn = sigmf(go) * tanhf(c);
    g_c[i] = c;
    g_h[i] = hn;
    g_z[b * ZDIM + 1024 + h] = hn;
    float hi = tf32r(hn);
    float lo = tf32r(hn - hi);
    write_afrag(b, h, hi);
    write_afrag(b, h + 512, hi);
    write_afrag(b, h + 1024, lo);
    if (h == 0) g_amax[b] = 0ull;
}

__global__ void k_emb(const float* __restrict__ emb) {
    int b = blockIdx.x, e = threadIdx.x;
    unsigned long long key = g_amax[b];
    int idx = (int)(0xFFFFFFFFu - (unsigned)(key & 0xFFFFFFFFull));
    g_z[b * ZDIM + e] = emb[(size_t)idx * EMBD + e];
}

// final transpose: scratch (b,t,v) -> out (b,v,t)
__global__ __launch_bounds__(256)
void k_tr(float* __restrict__ out) {
    __shared__ float sm[256 * 21];
    const int b = blockIdx.y;
    const int v0 = blockIdx.x * 256;
    const int tid = threadIdx.x;
    const float* src = g_scratch + (size_t)b * TT * VOC;
#pragma unroll
    for (int t = 0; t < TT; t++) sm[tid * 21 + t] = src[(size_t)t * VOC + v0 + tid];
    __syncthreads();
    float* ob = out + (size_t)b * VOC * TT + (size_t)v0 * TT;
    for (int e = tid; e < 256 * TT; e += 256) {
        int v = e / TT, t = e - v * TT;
        ob[e] = sm[v * 21 + t];
    }
}

// ---------------- host launch ----------------
static inline void* sym_addr(const void* symbol) {
    void* p = nullptr;
    cudaGetSymbolAddress(&p, symbol);
    return p;
}

extern "C" void kernel_launch(void* const* d_in, const int* in_sizes, int n_in,
                              void* d_out, int out_size) {
    const float* feat    = (const float*)d_in[0];
    const int*   caps    = (const int*)d_in[1];
    const float* W_ienc  = (const float*)d_in[2];
    const float* b_ienc  = (const float*)d_in[3];
    const float* W_oenc  = (const float*)d_in[4];
    const float* b_oenc  = (const float*)d_in[5];
    const float* W_att   = (const float*)d_in[6];
    const float* b_att   = (const float*)d_in[7];
    const float* W_inith = (const float*)d_in[8];
    const float* b_inith = (const float*)d_in[9];
    const float* W_initc = (const float*)d_in[10];
    const float* b_initc = (const float*)d_in[11];
    const float* W_gate  = (const float*)d_in[12];
    const float* b_gate  = (const float*)d_in[13];
    const float* embT    = (const float*)d_in[14];
    const float* W_lih   = (const float*)d_in[15];
    const float* W_lhh   = (const float*)d_in[16];
    const float* b_lih   = (const float*)d_in[17];
    const float* b_lhh   = (const float*)d_in[18];
    const float* W_out   = (const float*)d_in[19];
    const float* b_out   = (const float*)d_in[20];
    float* out = (float*)d_out;

    float* p_mean  = (float*)sym_addr(g_mean);
    float* p_h     = (float*)sym_addr(g_h);
    float* p_c     = (float*)sym_addr(g_c);
    float* p_q     = (float*)sym_addr(g_q);
    float* p_ctx   = (float*)sym_addr(g_ctx);
    float* p_z     = (float*)sym_addr(g_z);
    float* p_gates = (float*)sym_addr(g_gates);
    float* p_ka    = (float*)sym_addr(g_ka);
    float* p_Wcat  = (float*)sym_addr(g_Wcat);

    static bool attr_done = false;
    if (!attr_done) {
        cudaFuncSetAttribute(logits_mma, cudaFuncAttributeMaxDynamicSharedMemorySize, L_SMEM);
        attr_done = true;
    }

    // ---- setup (once per replay) ----
    {
        size_t nB = (size_t)NTILES * NKS * 32;
        k_bfrag<<<(unsigned)((nB + 255) / 256), 256>>>(W_out);
    }
    k_mean<<<BSZ, 512>>>(feat);
    gemm_small<4><<<dim3(HDIM / 64, BSZ / 16), 128>>>(p_mean, W_inith, b_inith, nullptr,
                                                      p_h, BSZ, HDIM, EDIM);
    gemm_small<0><<<dim3(HDIM / 64, BSZ / 16), 128>>>(p_mean, W_initc, b_initc, nullptr,
                                                      p_c, BSZ, HDIM, EDIM);
    sgemm_nt<<<dim3(ADIM / 128, (BSZ * PIX) / 128), 256>>>(feat, W_ienc, b_ienc,
                                                           p_ka, BSZ * PIX, ADIM, EDIM);
    k_x0<<<BSZ, 512>>>(caps, embT);
    k_pack<<<(G4 * ZDIM + 255) / 256, 256>>>(W_lih, W_lhh);

    // ---- T recurrent steps ----
    for (int t = 0; t < TT; t++) {
        gemm_small<0><<<dim3(ADIM / 64, BSZ / 16), 128>>>(p_h, W_oenc, b_oenc, nullptr,
                                                          p_q, BSZ, ADIM, HDIM);
        k_att<<<BSZ, 512>>>(feat, W_att, b_att);
        gemm_small<1><<<dim3(EDIM / 64, BSZ / 16), 128>>>(p_ctx, W_gate, b_gate, nullptr,
                                                          nullptr, BSZ, EDIM, EDIM);
        gemm_small<2><<<dim3(G4 / 64, BSZ / 16), 128>>>(p_z, p_Wcat, b_lih, b_lhh,
                                                        p_gates, BSZ, G4, ZDIM);
        k_cell<<<(BSZ * HDIM) / 256, 256>>>();
        // mma.sync tf32-split logits + fused argmax
        logits_mma<<<VOC / 128, 256, L_SMEM>>>(b_out, t);
        if (t < TT - 1) k_emb<<<BSZ, 512>>>(embT);
    }

    k_tr<<<dim3(VOC / 256, BSZ), 256>>>(out);
}